// round 10
// baseline (speedup 1.0000x reference)
#include <cuda_runtime.h>
#include <cuda_bf16.h>
#include <math.h>
#include <stdint.h>

#define NP   8192
#define DIM  128
#define NSTR 64               // 64 stripes of 128 rows
#define NCTA 148
#define NTHR 512

#define KLN2F  6.1996966f             // ln2/(sqrt_c*T)
#define KFULLF 8.944271909999159f     // 1/(sqrt_c*T)
#define TEMPF  0.5f
// negated Taylor of lg2(0.9025*dn), d = dn-1 in [-0.0975, 0.1025]
#define NC0  0.14801175f
#define NC1 -1.44269504f
#define NC2  0.72134752f
#define NC3 -0.48089835f
#define NC4  0.36067376f

#define LDS_ROW 272           // 128 bf16 + 8 pad

#define OFF_A0 0
#define OFF_A1 34816
#define OFF_B0 69632
#define OFF_B1 104448
#define OFF_B2 139264
#define SMEM_REQ 174080

typedef unsigned long long u64;

__device__ __nv_bfloat16 g_fb[NP * DIM];   // normalized features, bf16
__device__ int    g_lab[NP];               // packed (pl<<16)|sl
__device__ float2 g_stats2[NP];            // x=T (sum exp, excl diag), y=Sum L2(pos)

// ---------------- PTX helpers (base sm_103-safe) ----------------
__device__ __forceinline__ uint32_t smem_u32(const void* p) {
    uint32_t a;
    asm("{ .reg .u64 t; cvta.to.shared.u64 t, %1; cvt.u32.u64 %0, t; }" : "=r"(a) : "l"(p));
    return a;
}
__device__ __forceinline__ float f_sqrt(float x){float r;asm("sqrt.approx.f32 %0,%1;":"=f"(r):"f"(x));return r;}
__device__ __forceinline__ float f_lg2(float x){float r;asm("lg2.approx.f32 %0,%1;":"=f"(r):"f"(x));return r;}
__device__ __forceinline__ float f_ex2(float x){float r;asm("ex2.approx.f32 %0,%1;":"=f"(r):"f"(x));return r;}

// f32x2 packed math (PTX ISA sm_100+, base feature)
__device__ __forceinline__ u64 pk2(float lo, float hi){u64 r;asm("mov.b64 %0,{%1,%2};":"=l"(r):"f"(lo),"f"(hi));return r;}
__device__ __forceinline__ void upk2(float& lo, float& hi, u64 v){asm("mov.b64 {%0,%1},%2;":"=f"(lo),"=f"(hi):"l"(v));}
__device__ __forceinline__ u64 fma2_(u64 a, u64 b, u64 c){u64 d;asm("fma.rn.f32x2 %0,%1,%2,%3;":"=l"(d):"l"(a),"l"(b),"l"(c));return d;}
__device__ __forceinline__ u64 add2_(u64 a, u64 b){u64 d;asm("add.rn.f32x2 %0,%1,%2;":"=l"(d):"l"(a),"l"(b));return d;}
__device__ __forceinline__ u64 mul2_(u64 a, u64 b){u64 d;asm("mul.rn.f32x2 %0,%1,%2;":"=l"(d):"l"(a),"l"(b));return d;}

// vector reductions to global (sm_90+)
__device__ __forceinline__ void red2g(float* a, float x, float y){
    asm volatile("red.global.add.v2.f32 [%0],{%1,%2};" :: "l"(a), "f"(x), "f"(y) : "memory");
}
__device__ __forceinline__ void red4g(float* a, float x, float y, float z, float w){
    asm volatile("red.global.add.v4.f32 [%0],{%1,%2,%3,%4};" :: "l"(a), "f"(x), "f"(y), "f"(z), "f"(w) : "memory");
}

__device__ __forceinline__ void cp16(uint32_t dst, const void* src) {
    asm volatile("cp.async.cg.shared.global [%0], [%1], 16;" :: "r"(dst), "l"(src) : "memory");
}
#define CP_COMMIT() asm volatile("cp.async.commit_group;" ::: "memory")
#define CP_WAIT(n)  asm volatile("cp.async.wait_group %0;" :: "n"(n) : "memory")

__device__ __forceinline__ void ldsm4(uint32_t& r0, uint32_t& r1, uint32_t& r2, uint32_t& r3,
                                      uint32_t addr) {
    asm volatile("ldmatrix.sync.aligned.m8n8.x4.shared.b16 {%0,%1,%2,%3}, [%4];"
                 : "=r"(r0), "=r"(r1), "=r"(r2), "=r"(r3) : "r"(addr));
}
__device__ __forceinline__ void mma16816(float* c, const uint32_t* a, const uint32_t* b) {
    asm volatile(
        "mma.sync.aligned.m16n8k16.row.col.f32.bf16.bf16.f32 "
        "{%0,%1,%2,%3}, {%4,%5,%6,%7}, {%8,%9}, {%0,%1,%2,%3};"
        : "+f"(c[0]), "+f"(c[1]), "+f"(c[2]), "+f"(c[3])
        : "r"(a[0]), "r"(a[1]), "r"(a[2]), "r"(a[3]), "r"(b[0]), "r"(b[1]));
}

// ---------------------------------------------------------------------------
// 2 rows per warp for doubled MLP
__global__ void norm_kernel(const float* __restrict__ feat,
                            const int* __restrict__ pl, const int* __restrict__ sl) {
    int r0   = blockIdx.x * 16 + (threadIdx.x >> 5) * 2;
    int r1   = r0 + 1;
    int lane = threadIdx.x & 31;
    float4 v0 = ((const float4*)(feat + r0 * DIM))[lane];
    float4 v1 = ((const float4*)(feat + r1 * DIM))[lane];
    float s0 = v0.x*v0.x + v0.y*v0.y + v0.z*v0.z + v0.w*v0.w;
    float s1 = v1.x*v1.x + v1.y*v1.y + v1.z*v1.z + v1.w*v1.w;
    #pragma unroll
    for (int o = 16; o; o >>= 1) {
        s0 += __shfl_xor_sync(0xffffffffu, s0, o);
        s1 += __shfl_xor_sync(0xffffffffu, s1, o);
    }
    float i0 = 1.0f / fmaxf(sqrtf(s0), 1e-12f);
    float i1 = 1.0f / fmaxf(sqrtf(s1), 1e-12f);
    {
        __nv_bfloat162 p0 = __floats2bfloat162_rn(v0.x*i0, v0.y*i0);
        __nv_bfloat162 p1 = __floats2bfloat162_rn(v0.z*i0, v0.w*i0);
        uint2 w; w.x = *reinterpret_cast<uint32_t*>(&p0); w.y = *reinterpret_cast<uint32_t*>(&p1);
        ((uint2*)g_fb)[r0 * 32 + lane] = w;
    }
    {
        __nv_bfloat162 p0 = __floats2bfloat162_rn(v1.x*i1, v1.y*i1);
        __nv_bfloat162 p1 = __floats2bfloat162_rn(v1.z*i1, v1.w*i1);
        uint2 w; w.x = *reinterpret_cast<uint32_t*>(&p0); w.y = *reinterpret_cast<uint32_t*>(&p1);
        ((uint2*)g_fb)[r1 * 32 + lane] = w;
    }
    if (lane == 0) g_lab[r0] = (pl[r0] << 16) | (sl[r0] & 0xFFFF);
    if (lane == 1) g_lab[r1] = (pl[r1] << 16) | (sl[r1] & 0xFFFF);
    if (threadIdx.x < 16) g_stats2[blockIdx.x * 16 + threadIdx.x] = make_float2(0.f, 0.f);
}

// cp.async one 128x128 bf16 tile into padded SMEM (512 thr)
__device__ __forceinline__ void cp_tile(uint32_t udst, const char* gsrc, int tid) {
    #pragma unroll
    for (int it = 0; it < 4; it++) {
        int idx = tid + it * NTHR;
        int row = idx >> 4;
        int ch  = idx & 15;
        cp16(udst + row * LDS_ROW + ch * 16, gsrc + row * 256 + ch * 16);
    }
}

// ---------------------------------------------------------------------------
__global__ void __launch_bounds__(NTHR, 1)
pair_kernel() {
    extern __shared__ __align__(16) char sm[];
    const uint32_t ub = smem_u32(sm);
    const uint32_t boffs[3] = {ub + OFF_B0, ub + OFF_B1, ub + OFF_B2};

    const int tid  = threadIdx.x;
    const int wid  = tid >> 5;
    const int lane = tid & 31;
    const int wm   = wid & 3;
    const int wn   = wid >> 2;
    const char* gsrc = (const char*)g_fb;

    const int cta  = blockIdx.x;
    const int t0   = cta * 14 + (cta < 8 ? cta : 8);
    const int tend = t0 + 14 + (cta < 8 ? 1 : 0);

    int I = 0, base = 0;
    while (base + (NSTR - I) <= t0) { base += NSTR - I; I++; }
    int J = I + (t0 - base);

    cp_tile(ub + OFF_A0, gsrc + (size_t)I * 128 * 256, tid);
    cp_tile(boffs[0],    gsrc + (size_t)J * 128 * 256, tid);
    CP_COMMIT();
    int abuf = 0;

    // ldmatrix lane offsets
    const int g  = lane >> 3;
    const int lr = lane & 7;
    uint32_t aoff[2], boff[2];
    #pragma unroll
    for (int a = 0; a < 2; a++)
        aoff[a] = (uint32_t)((wm * 32 + a * 16 + (g & 1) * 8 + lr) * LDS_ROW + (g >> 1) * 16);
    #pragma unroll
    for (int p = 0; p < 2; p++)
        boff[p] = (uint32_t)((wn * 32 + p * 16 + (g >> 1) * 8 + lr) * LDS_ROW + (g & 1) * 16);

    int grow[4], pk[4];
    #pragma unroll
    for (int rr = 0; rr < 4; rr++) {
        grow[rr] = I * 128 + wm * 32 + (rr >> 1) * 16 + (rr & 1) * 8 + (lane >> 2);
        pk[rr]   = g_lab[grow[rr]];
    }
    u64 T2[4] = {0,0,0,0}, Ap2[4] = {0,0,0,0};

    // packed constants (loop-invariant)
    const u64 C_M11 = pk2(-11.025f, -11.025f);
    const u64 C_Q10 = pk2(10.025f, 10.025f);
    const u64 C_M01 = pk2(-0.1f, -0.1f);
    const u64 C_DN  = pk2(1.0025f, 1.0025f);
    const u64 C_D0  = pk2(0.0025f, 0.0025f);
    const u64 C_P01 = pk2(0.1f, 0.1f);
    const u64 C_TWO = pk2(2.0f, 2.0f);
    const u64 C_MK  = pk2(-KFULLF, -KFULLF);
    const u64 C_N4  = pk2(NC4, NC4);
    const u64 C_N3  = pk2(NC3, NC3);
    const u64 C_N2  = pk2(NC2, NC2);
    const u64 C_N1  = pk2(NC1, NC1);
    const u64 C_N0  = pk2(NC0, NC0);

    const int2* glab2 = (const int2*)g_lab;

    for (int t = t0; t < tend; t++) {
        int In = I, Jn = J + 1;
        if (Jn == NSTR) { In = I + 1; Jn = In; }
        const bool last = (t + 1 >= tend);
        const int  slot = (t - t0) % 3;

        if (!last) {
            cp_tile(boffs[(t - t0 + 1) % 3], gsrc + (size_t)Jn * 128 * 256, tid);
            if (In != I)
                cp_tile(ub + (abuf ? OFF_A0 : OFF_A1), gsrc + (size_t)In * 128 * 256, tid);
            CP_COMMIT();
            CP_WAIT(1);
        } else {
            CP_WAIT(0);
        }
        __syncthreads();

        const uint32_t uA = ub + (abuf ? OFF_A1 : OFF_A0);
        const uint32_t uB = boffs[slot];

        float acc[2][4][4];
        #pragma unroll
        for (int a = 0; a < 2; a++)
            #pragma unroll
            for (int b = 0; b < 4; b++)
                #pragma unroll
                for (int j = 0; j < 4; j++) acc[a][b][j] = 0.0f;

        #pragma unroll
        for (int ks = 0; ks < 8; ks++) {
            const uint32_t kb = (uint32_t)(ks * 32);
            uint32_t af[2][4], bf[4][2];
            #pragma unroll
            for (int a = 0; a < 2; a++)
                ldsm4(af[a][0], af[a][1], af[a][2], af[a][3], uA + aoff[a] + kb);
            #pragma unroll
            for (int p = 0; p < 2; p++)
                ldsm4(bf[2*p][0], bf[2*p][1], bf[2*p+1][0], bf[2*p+1][1], uB + boff[p] + kb);
            #pragma unroll
            for (int a = 0; a < 2; a++)
                #pragma unroll
                for (int b = 0; b < 4; b++)
                    mma16816(acc[a][b], af[a], bf[b]);
        }

        // ---- epilogue (f32x2 packed; pair = (even,odd) column) ----
        const int  jt = J * 128;
        const bool offdiag = (J != I);
        #pragma unroll
        for (int b = 0; b < 4; b++) {
            const int li  = wn * 32 + b * 8 + ((lane & 3) << 1);
            const int2 pkc = glab2[(jt + li) >> 1];
            u64 Tc2 = 0, Ac2 = 0;
            #pragma unroll
            for (int p = 0; p < 4; p++) {
                float slo = acc[p >> 1][b][(p & 1) * 2];
                float shi = acc[p >> 1][b][(p & 1) * 2 + 1];
                u64 s2 = pk2(slo, shi);
                u64 q2 = fma2_(s2, C_M11, C_Q10);
                u64 t2 = fma2_(s2, s2, q2);                 // (1-s)(10.025-s)
                float tl, th; upk2(tl, th, t2);
                float sql = f_sqrt(fmaxf(tl, 0.0f));
                float sqh = f_sqrt(fmaxf(th, 0.0f));
                u64 dn2  = fma2_(s2, C_M01, C_DN);
                u64 arg2 = fma2_(pk2(sql, sqh), C_P01, dn2);
                float al, ah; upk2(al, ah, arg2);
                u64 l12 = pk2(f_lg2(al), f_lg2(ah));
                u64 d2  = fma2_(s2, C_M01, C_D0);           // dn - 1
                u64 pn  = fma2_(d2, C_N4, C_N3);
                pn = fma2_(d2, pn, C_N2);
                pn = fma2_(d2, pn, C_N1);
                pn = fma2_(d2, pn, C_N0);                   // -lg2(0.9025*dn)
                u64 L22 = fma2_(l12, C_TWO, pn);
                u64 ek2 = mul2_(L22, C_MK);
                float ekl, ekh; upk2(ekl, ekh, ek2);
                u64 e2 = pk2(f_ex2(ekl), f_ex2(ekh));
                // label masks
                unsigned dx0 = (unsigned)(pk[p] ^ pkc.x);
                unsigned dx1 = (unsigned)(pk[p] ^ pkc.y);
                bool sp0 = (dx0 < 0x10000u) | ((dx0 & 0xFFFFu) == 0u);
                bool sp1 = (dx1 < 0x10000u) | ((dx1 & 0xFFFFu) == 0u);
                if (offdiag) {
                    u64 m2 = pk2(sp0 ? 1.0f : 0.0f, sp1 ? 1.0f : 0.0f);
                    T2[p]  = add2_(T2[p], e2);
                    Ap2[p] = fma2_(L22, m2, Ap2[p]);
                    Tc2    = add2_(Tc2, e2);
                    Ac2    = fma2_(L22, m2, Ac2);
                } else {
                    bool dg0 = (jt + li     == grow[p]);
                    bool dg1 = (jt + li + 1 == grow[p]);
                    u64 m2 = pk2((sp0 && !dg0) ? 1.0f : 0.0f, (sp1 && !dg1) ? 1.0f : 0.0f);
                    u64 n2 = pk2(dg0 ? 0.0f : 1.0f, dg1 ? 0.0f : 1.0f);
                    T2[p]  = fma2_(e2, n2, T2[p]);
                    Ap2[p] = fma2_(L22, m2, Ap2[p]);
                }
            }
            if (offdiag) {   // mirror column sums into stripe J rows
                float Tc0, Tc1, Ac0, Ac1;
                upk2(Tc0, Tc1, Tc2);
                upk2(Ac0, Ac1, Ac2);
                #pragma unroll
                for (int o = 4; o <= 16; o <<= 1) {
                    Tc0 += __shfl_xor_sync(0xffffffffu, Tc0, o);
                    Ac0 += __shfl_xor_sync(0xffffffffu, Ac0, o);
                    Tc1 += __shfl_xor_sync(0xffffffffu, Tc1, o);
                    Ac1 += __shfl_xor_sync(0xffffffffu, Ac1, o);
                }
                if (lane < 4)
                    red4g((float*)&g_stats2[jt + li], Tc0, Ac0, Tc1, Ac1);
            }
        }

        // row-stat flush on stripe change / end
        if (last || In != I) {
            #pragma unroll
            for (int rr = 0; rr < 4; rr++) {
                float ta, tb, aa, ab;
                upk2(ta, tb, T2[rr]);
                upk2(aa, ab, Ap2[rr]);
                float tr = ta + tb, ar = aa + ab;
                #pragma unroll
                for (int o = 1; o <= 2; o <<= 1) {
                    tr += __shfl_xor_sync(0xffffffffu, tr, o);
                    ar += __shfl_xor_sync(0xffffffffu, ar, o);
                }
                if ((lane & 3) == 0)
                    red2g((float*)&g_stats2[grow[rr]], tr, ar);
                T2[rr] = 0; Ap2[rr] = 0;
            }
            if (!last && In != I) {
                abuf ^= 1;
                #pragma unroll
                for (int rr = 0; rr < 4; rr++) {
                    grow[rr] = In * 128 + wm * 32 + (rr >> 1) * 16 + (rr & 1) * 8 + (lane >> 2);
                    pk[rr]   = g_lab[grow[rr]];
                }
            }
        }
        if (!last) { I = In; J = Jn; }
    }
}

// ---------------------------------------------------------------------------
// finalize: label histograms (num_pos) + row reduction -> scalar loss
__global__ void finalize_kernel(float* __restrict__ out) {
    __shared__ int hcp[32], hcs[16], hcj[512];
    __shared__ float ssum[32], scnt[32];
    int tid = threadIdx.x;  // 1024
    if (tid < 512) hcj[tid] = 0;
    if (tid < 32)  hcp[tid] = 0;
    if (tid < 16)  hcs[tid] = 0;
    __syncthreads();
    for (int i = tid; i < NP; i += 1024) {
        int pkv = g_lab[i];
        int p = pkv >> 16, s2 = pkv & 0xFFFF;
        atomicAdd(&hcp[p], 1);
        atomicAdd(&hcs[s2], 1);
        atomicAdd(&hcj[p * 16 + s2], 1);
    }
    __syncthreads();

    float sum = 0.0f, nv = 0.0f;
    for (int i = tid; i < NP; i += 1024) {
        int pkv = g_lab[i];
        int p = pkv >> 16, s2 = pkv & 0xFFFF;
        float np = (float)(hcp[p] + hcs[s2] - hcj[p * 16 + s2] - 1);
        float2 st = g_stats2[i];
        if (np > 0.0f) {
            float den = st.x + 1e-8f;
            sum += (-KLN2F * st.y - np * __logf(den)) / np;
            nv  += 1.0f;
        }
    }
    #pragma unroll
    for (int o = 16; o; o >>= 1) {
        sum += __shfl_xor_sync(0xffffffffu, sum, o);
        nv  += __shfl_xor_sync(0xffffffffu, nv,  o);
    }
    if ((tid & 31) == 0) { ssum[tid >> 5] = sum; scnt[tid >> 5] = nv; }
    __syncthreads();
    if (tid < 32) {
        sum = ssum[tid]; nv = scnt[tid];
        #pragma unroll
        for (int o = 16; o; o >>= 1) {
            sum += __shfl_xor_sync(0xffffffffu, sum, o);
            nv  += __shfl_xor_sync(0xffffffffu, nv,  o);
        }
        if (tid == 0) {
            float loss = 0.0f;
            if (nv > 0.0f) loss = -sum / fmaxf(nv, 1.0f) * TEMPF;
            if (!isfinite(loss)) loss = 0.0f;
            out[0] = loss;
        }
    }
}

// ---------------------------------------------------------------------------
extern "C" void kernel_launch(void* const* d_in, const int* in_sizes, int n_in,
                              void* d_out, int out_size) {
    const float* feat = (const float*)d_in[0];
    const int*   pl   = (const int*)d_in[1];
    const int*   sl   = (const int*)d_in[2];
    float* out = (float*)d_out;

    cudaFuncSetAttribute(pair_kernel, cudaFuncAttributeMaxDynamicSharedMemorySize, SMEM_REQ);

    norm_kernel<<<NP / 16, 256>>>(feat, pl, sl);
    pair_kernel<<<NCTA, NTHR, SMEM_REQ>>>();
    finalize_kernel<<<1, 1024>>>(out);
}

// round 16
// speedup vs baseline: 1.0077x; 1.0077x over previous
#include <cuda_runtime.h>
#include <cuda_bf16.h>
#include <math.h>
#include <stdint.h>

#define NP   8192
#define DIM  128
#define NSTR 64               // 64 stripes of 128 rows
#define NCTA 148
#define NTHR 512

#define KLN2F  6.1996966f             // ln2/(sqrt_c*T)
#define KFULLF 8.944271909999159f     // 1/(sqrt_c*T)
#define TEMPF  0.5f
#define LG09   -0.14801175f           // lg2(0.9025)
// Taylor of lg2(1+d), d = dn-1 in [-0.0975, 0.1025]
#define PC1  1.44269504f
#define PC2 -0.72134752f
#define PC3  0.48089835f
#define PC4 -0.36067376f

#define LDS_ROW 272           // 128 bf16 + 8 pad

#define OFF_A0 0
#define OFF_A1 34816
#define OFF_B0 69632
#define OFF_B1 104448
#define OFF_B2 139264
#define SMEM_REQ 174080

__device__ __nv_bfloat16 g_fb[NP * DIM];   // normalized features, bf16
__device__ int    g_lab[NP];               // packed (pl<<16)|sl
__device__ float2 g_stats2[NP];            // x=T (sum exp, excl diag), y=Sum L2(pos)

// ---------------- PTX helpers (base sm_103-safe) ----------------
__device__ __forceinline__ uint32_t smem_u32(const void* p) {
    uint32_t a;
    asm("{ .reg .u64 t; cvta.to.shared.u64 t, %1; cvt.u32.u64 %0, t; }" : "=r"(a) : "l"(p));
    return a;
}
__device__ __forceinline__ float f_sqrt(float x){float r;asm("sqrt.approx.f32 %0,%1;":"=f"(r):"f"(x));return r;}
__device__ __forceinline__ float f_lg2(float x){float r;asm("lg2.approx.f32 %0,%1;":"=f"(r):"f"(x));return r;}
__device__ __forceinline__ float f_ex2(float x){float r;asm("ex2.approx.f32 %0,%1;":"=f"(r):"f"(x));return r;}

// vector reductions to global (sm_90+)
__device__ __forceinline__ void red2g(float* a, float x, float y){
    asm volatile("red.global.add.v2.f32 [%0],{%1,%2};" :: "l"(a), "f"(x), "f"(y) : "memory");
}
__device__ __forceinline__ void red4g(float* a, float x, float y, float z, float w){
    asm volatile("red.global.add.v4.f32 [%0],{%1,%2,%3,%4};" :: "l"(a), "f"(x), "f"(y), "f"(z), "f"(w) : "memory");
}

__device__ __forceinline__ void cp16(uint32_t dst, const void* src) {
    asm volatile("cp.async.cg.shared.global [%0], [%1], 16;" :: "r"(dst), "l"(src) : "memory");
}
#define CP_COMMIT() asm volatile("cp.async.commit_group;" ::: "memory")
#define CP_WAIT(n)  asm volatile("cp.async.wait_group %0;" :: "n"(n) : "memory")

__device__ __forceinline__ void ldsm4(uint32_t& r0, uint32_t& r1, uint32_t& r2, uint32_t& r3,
                                      uint32_t addr) {
    asm volatile("ldmatrix.sync.aligned.m8n8.x4.shared.b16 {%0,%1,%2,%3}, [%4];"
                 : "=r"(r0), "=r"(r1), "=r"(r2), "=r"(r3) : "r"(addr));
}
__device__ __forceinline__ void mma16816(float* c, const uint32_t* a, const uint32_t* b) {
    asm volatile(
        "mma.sync.aligned.m16n8k16.row.col.f32.bf16.bf16.f32 "
        "{%0,%1,%2,%3}, {%4,%5,%6,%7}, {%8,%9}, {%0,%1,%2,%3};"
        : "+f"(c[0]), "+f"(c[1]), "+f"(c[2]), "+f"(c[3])
        : "r"(a[0]), "r"(a[1]), "r"(a[2]), "r"(a[3]), "r"(b[0]), "r"(b[1]));
}

// ---------------------------------------------------------------------------
// 2 rows per warp
__global__ void norm_kernel(const float* __restrict__ feat,
                            const int* __restrict__ pl, const int* __restrict__ sl) {
    int r0   = blockIdx.x * 16 + (threadIdx.x >> 5) * 2;
    int r1   = r0 + 1;
    int lane = threadIdx.x & 31;
    float4 v0 = ((const float4*)(feat + r0 * DIM))[lane];
    float4 v1 = ((const float4*)(feat + r1 * DIM))[lane];
    float s0 = v0.x*v0.x + v0.y*v0.y + v0.z*v0.z + v0.w*v0.w;
    float s1 = v1.x*v1.x + v1.y*v1.y + v1.z*v1.z + v1.w*v1.w;
    #pragma unroll
    for (int o = 16; o; o >>= 1) {
        s0 += __shfl_xor_sync(0xffffffffu, s0, o);
        s1 += __shfl_xor_sync(0xffffffffu, s1, o);
    }
    float i0 = 1.0f / fmaxf(sqrtf(s0), 1e-12f);
    float i1 = 1.0f / fmaxf(sqrtf(s1), 1e-12f);
    {
        __nv_bfloat162 p0 = __floats2bfloat162_rn(v0.x*i0, v0.y*i0);
        __nv_bfloat162 p1 = __floats2bfloat162_rn(v0.z*i0, v0.w*i0);
        uint2 w; w.x = *reinterpret_cast<uint32_t*>(&p0); w.y = *reinterpret_cast<uint32_t*>(&p1);
        ((uint2*)g_fb)[r0 * 32 + lane] = w;
    }
    {
        __nv_bfloat162 p0 = __floats2bfloat162_rn(v1.x*i1, v1.y*i1);
        __nv_bfloat162 p1 = __floats2bfloat162_rn(v1.z*i1, v1.w*i1);
        uint2 w; w.x = *reinterpret_cast<uint32_t*>(&p0); w.y = *reinterpret_cast<uint32_t*>(&p1);
        ((uint2*)g_fb)[r1 * 32 + lane] = w;
    }
    if (lane == 0) g_lab[r0] = (pl[r0] << 16) | (sl[r0] & 0xFFFF);
    if (lane == 1) g_lab[r1] = (pl[r1] << 16) | (sl[r1] & 0xFFFF);
    if (threadIdx.x < 16) g_stats2[blockIdx.x * 16 + threadIdx.x] = make_float2(0.f, 0.f);
}

// cp.async one 128x128 bf16 tile into padded SMEM (512 thr)
__device__ __forceinline__ void cp_tile(uint32_t udst, const char* gsrc, int tid) {
    #pragma unroll
    for (int it = 0; it < 4; it++) {
        int idx = tid + it * NTHR;
        int row = idx >> 4;
        int ch  = idx & 15;
        cp16(udst + row * LDS_ROW + ch * 16, gsrc + row * 256 + ch * 16);
    }
}

// ---------------------------------------------------------------------------
__global__ void __launch_bounds__(NTHR, 1)
pair_kernel() {
    extern __shared__ __align__(16) char sm[];
    const uint32_t ub = smem_u32(sm);
    const uint32_t boffs3[3] = {ub + OFF_B0, ub + OFF_B1, ub + OFF_B2};

    const int tid  = threadIdx.x;
    const int wid  = tid >> 5;
    const int lane = tid & 31;
    const int wm   = wid & 3;
    const int wn   = wid >> 2;
    const char* gsrc = (const char*)g_fb;

    const int cta  = blockIdx.x;
    const int t0   = cta * 14 + (cta < 8 ? cta : 8);
    const int tend = t0 + 14 + (cta < 8 ? 1 : 0);

    int I = 0, base = 0;
    while (base + (NSTR - I) <= t0) { base += NSTR - I; I++; }
    int J = I + (t0 - base);

    cp_tile(ub + OFF_A0, gsrc + (size_t)I * 128 * 256, tid);
    cp_tile(boffs3[0],   gsrc + (size_t)J * 128 * 256, tid);
    CP_COMMIT();
    int abuf = 0;

    // ldmatrix lane offsets
    const int g  = lane >> 3;
    const int lr = lane & 7;
    uint32_t aoff[2], boff[2];
    #pragma unroll
    for (int a = 0; a < 2; a++)
        aoff[a] = (uint32_t)((wm * 32 + a * 16 + (g & 1) * 8 + lr) * LDS_ROW + (g >> 1) * 16);
    #pragma unroll
    for (int p = 0; p < 2; p++)
        boff[p] = (uint32_t)((wn * 32 + p * 16 + (g >> 1) * 8 + lr) * LDS_ROW + (g & 1) * 16);

    int grow[4], pk[4];
    #pragma unroll
    for (int rr = 0; rr < 4; rr++) {
        grow[rr] = I * 128 + wm * 32 + (rr >> 1) * 16 + (rr & 1) * 8 + (lane >> 2);
        pk[rr]   = g_lab[grow[rr]];
    }
    float T[4] = {0,0,0,0}, Ap[4] = {0,0,0,0};

    const int2* glab2 = (const int2*)g_lab;

    for (int t = t0; t < tend; t++) {
        int In = I, Jn = J + 1;
        if (Jn == NSTR) { In = I + 1; Jn = In; }
        const bool last = (t + 1 >= tend);
        const int  slot = (t - t0) % 3;

        if (!last) {
            cp_tile(boffs3[(t - t0 + 1) % 3], gsrc + (size_t)Jn * 128 * 256, tid);
            if (In != I)
                cp_tile(ub + (abuf ? OFF_A0 : OFF_A1), gsrc + (size_t)In * 128 * 256, tid);
            CP_COMMIT();
            CP_WAIT(1);
        } else {
            CP_WAIT(0);
        }
        __syncthreads();

        const uint32_t uA = ub + (abuf ? OFF_A1 : OFF_A0);
        const uint32_t uB = boffs3[slot];

        float acc[2][4][4];
        #pragma unroll
        for (int a = 0; a < 2; a++)
            #pragma unroll
            for (int b = 0; b < 4; b++)
                #pragma unroll
                for (int j = 0; j < 4; j++) acc[a][b][j] = 0.0f;

        // ---- MMA, n-half outer so acc[.][0..1] completes at ~50% of drain ----
        #pragma unroll
        for (int h = 0; h < 2; h++) {
            #pragma unroll
            for (int ks = 0; ks < 8; ks++) {
                const uint32_t kb = (uint32_t)(ks * 32);
                uint32_t af[2][4], bf[2][2];
                #pragma unroll
                for (int a = 0; a < 2; a++)
                    ldsm4(af[a][0], af[a][1], af[a][2], af[a][3], uA + aoff[a] + kb);
                ldsm4(bf[0][0], bf[0][1], bf[1][0], bf[1][1], uB + boff[h] + kb);
                #pragma unroll
                for (int a = 0; a < 2; a++) {
                    mma16816(acc[a][2*h],     af[a], bf[0]);
                    mma16816(acc[a][2*h + 1], af[a], bf[1]);
                }
            }
        }

        // ---- epilogue (SoA-staged; column partials kept in regs, shuffled once) ----
        const int  jt = J * 128;
        const bool offdiag = (J != I);
        float TcB[4][2], AcB[4][2];
        #pragma unroll
        for (int b = 0; b < 4; b++) {
            const int li  = wn * 32 + b * 8 + ((lane & 3) << 1);
            const int2 pk2 = glab2[(jt + li) >> 1];

            float s8[8], sq8[8], l18[8], L28[8], e8[8];
            #pragma unroll
            for (int i = 0; i < 8; i++) s8[i] = acc[i >> 2][b][i & 3];

            #pragma unroll
            for (int i = 0; i < 8; i++) {          // stage 1: sqrt
                float q  = fmaf(-11.025f, s8[i], 10.025f);
                float t2 = fmaf(s8[i], s8[i], q);
                sq8[i] = f_sqrt(fmaxf(t2, 0.0f));
            }
            #pragma unroll
            for (int i = 0; i < 8; i++) {          // stage 2: lg2
                float dn  = fmaf(-0.1f, s8[i], 1.0025f);
                l18[i] = f_lg2(fmaf(0.1f, sq8[i], dn));
            }
            #pragma unroll
            for (int i = 0; i < 8; i++) {          // stage 3: poly + ex2
                float d  = fmaf(-0.1f, s8[i], 0.0025f);   // dn - 1
                float in3 = fmaf(d, PC4, PC3);
                float in2 = fmaf(d, in3, PC2);
                float in1 = fmaf(d, in2, PC1);
                float pc  = fmaf(d, in1, LG09);           // lg2(0.9025*dn)
                float L2  = fmaf(2.0f, l18[i], -pc);
                L28[i] = L2;
                e8[i]  = f_ex2(-KFULLF * L2);
            }

            if (offdiag) {
                float Tc0 = 0.f, Ac0 = 0.f, Tc1 = 0.f, Ac1 = 0.f;
                #pragma unroll
                for (int i = 0; i < 8; i++) {
                    const int rr = (i >> 2) * 2 + ((i & 3) >> 1);
                    const int pkj = (i & 1) ? pk2.y : pk2.x;
                    unsigned dx = (unsigned)(pk[rr] ^ pkj);
                    bool sp = (dx < 0x10000u) | ((dx & 0xFFFFu) == 0u);
                    float lpos = sp ? L28[i] : 0.0f;
                    T[rr] += e8[i]; Ap[rr] += lpos;
                    if (i & 1) { Tc1 += e8[i]; Ac1 += lpos; }
                    else       { Tc0 += e8[i]; Ac0 += lpos; }
                }
                TcB[b][0] = Tc0; TcB[b][1] = Tc1;
                AcB[b][0] = Ac0; AcB[b][1] = Ac1;
            } else {
                #pragma unroll
                for (int i = 0; i < 8; i++) {
                    const int rr  = (i >> 2) * 2 + ((i & 3) >> 1);
                    const int col = jt + li + (i & 1);
                    const int pkj = (i & 1) ? pk2.y : pk2.x;
                    unsigned dx = (unsigned)(pk[rr] ^ pkj);
                    bool dg = (col == grow[rr]);
                    bool sp = ((dx < 0x10000u) | ((dx & 0xFFFFu) == 0u)) && !dg;
                    T[rr]  += dg ? 0.0f : e8[i];
                    Ap[rr] += sp ? L28[i] : 0.0f;
                }
            }
        }

        if (offdiag) {
            // 16 independent 3-round shuffle chains (latency overlaps)
            #pragma unroll
            for (int o = 4; o <= 16; o <<= 1) {
                #pragma unroll
                for (int b = 0; b < 4; b++) {
                    TcB[b][0] += __shfl_xor_sync(0xffffffffu, TcB[b][0], o);
                    AcB[b][0] += __shfl_xor_sync(0xffffffffu, AcB[b][0], o);
                    TcB[b][1] += __shfl_xor_sync(0xffffffffu, TcB[b][1], o);
                    AcB[b][1] += __shfl_xor_sync(0xffffffffu, AcB[b][1], o);
                }
            }
            if (lane < 4) {
                #pragma unroll
                for (int b = 0; b < 4; b++) {
                    const int li = wn * 32 + b * 8 + ((lane & 3) << 1);
                    red4g((float*)&g_stats2[jt + li],
                          TcB[b][0], AcB[b][0], TcB[b][1], AcB[b][1]);
                }
            }
        }

        // row-stat flush on stripe change / end
        if (last || In != I) {
            #pragma unroll
            for (int rr = 0; rr < 4; rr++) {
                float tr = T[rr], ar = Ap[rr];
                #pragma unroll
                for (int o = 1; o <= 2; o <<= 1) {
                    tr += __shfl_xor_sync(0xffffffffu, tr, o);
                    ar += __shfl_xor_sync(0xffffffffu, ar, o);
                }
                if ((lane & 3) == 0)
                    red2g((float*)&g_stats2[grow[rr]], tr, ar);
                T[rr] = 0.f; Ap[rr] = 0.f;
            }
            if (!last && In != I) {
                abuf ^= 1;
                #pragma unroll
                for (int rr = 0; rr < 4; rr++) {
                    grow[rr] = In * 128 + wm * 32 + (rr >> 1) * 16 + (rr & 1) * 8 + (lane >> 2);
                    pk[rr]   = g_lab[grow[rr]];
                }
            }
        }
        if (!last) { I = In; J = Jn; }
    }
}

// ---------------------------------------------------------------------------
// finalize: label histograms (num_pos) + row reduction -> scalar loss
__global__ void finalize_kernel(float* __restrict__ out) {
    __shared__ int hcp[32], hcs[16], hcj[512];
    __shared__ float ssum[32], scnt[32];
    int tid = threadIdx.x;  // 1024
    if (tid < 512) hcj[tid] = 0;
    if (tid < 32)  hcp[tid] = 0;
    if (tid < 16)  hcs[tid] = 0;
    __syncthreads();
    for (int i = tid; i < NP; i += 1024) {
        int pkv = g_lab[i];
        int p = pkv >> 16, s2 = pkv & 0xFFFF;
        atomicAdd(&hcp[p], 1);
        atomicAdd(&hcs[s2], 1);
        atomicAdd(&hcj[p * 16 + s2], 1);
    }
    __syncthreads();

    float sum = 0.0f, nv = 0.0f;
    for (int i = tid; i < NP; i += 1024) {
        int pkv = g_lab[i];
        int p = pkv >> 16, s2 = pkv & 0xFFFF;
        float np = (float)(hcp[p] + hcs[s2] - hcj[p * 16 + s2] - 1);
        float2 st = g_stats2[i];
        if (np > 0.0f) {
            float den = st.x + 1e-8f;
            sum += (-KLN2F * st.y - np * __logf(den)) / np;
            nv  += 1.0f;
        }
    }
    #pragma unroll
    for (int o = 16; o; o >>= 1) {
        sum += __shfl_xor_sync(0xffffffffu, sum, o);
        nv  += __shfl_xor_sync(0xffffffffu, nv,  o);
    }
    if ((tid & 31) == 0) { ssum[tid >> 5] = sum; scnt[tid >> 5] = nv; }
    __syncthreads();
    if (tid < 32) {
        sum = ssum[tid]; nv = scnt[tid];
        #pragma unroll
        for (int o = 16; o; o >>= 1) {
            sum += __shfl_xor_sync(0xffffffffu, sum, o);
            nv  += __shfl_xor_sync(0xffffffffu, nv,  o);
        }
        if (tid == 0) {
            float loss = 0.0f;
            if (nv > 0.0f) loss = -sum / fmaxf(nv, 1.0f) * TEMPF;
            if (!isfinite(loss)) loss = 0.0f;
            out[0] = loss;
        }
    }
}

// ---------------------------------------------------------------------------
extern "C" void kernel_launch(void* const* d_in, const int* in_sizes, int n_in,
                              void* d_out, int out_size) {
    const float* feat = (const float*)d_in[0];
    const int*   pl   = (const int*)d_in[1];
    const int*   sl   = (const int*)d_in[2];
    float* out = (float*)d_out;

    cudaFuncSetAttribute(pair_kernel, cudaFuncAttributeMaxDynamicSharedMemorySize, SMEM_REQ);

    norm_kernel<<<NP / 16, 256>>>(feat, pl, sl);
    pair_kernel<<<NCTA, NTHR, SMEM_REQ>>>();
    finalize_kernel<<<1, 1024>>>(out);
}